// round 15
// baseline (speedup 1.0000x reference)
#include <cuda_runtime.h>

// OriginNoiseBilateral FINAL (converged): 17x17 bilateral, 8x3x512x512 fp32 NCHW.
// Grid-launched, V=4 outputs/thread as 2 packed f32x2 pairs, 48x48 float4
// halo tile, thread-invariant dy^2 smem table, lb(256,3), mid-row unroll x2,
// carry-stepped halo load.
//
// Convergence evidence (14 bench rounds):
//   - core = 8 packed f32x2 ops + 2 EX2 per pair-tap; FFMA2 with 3 distinct
//     u64 operands runs rt=3 under RF banking -> 22 SMSP-cyc/pair-tap floor.
//   - measured 24.0 cyc/pair-tap (190.5us); fma busy 71% == predicted 16.8/24.
//   - TLP, scratch regs, unroll, .reuse, persistence, V in {4,6,8}, f16 exp,
//     and all alternative math formulations benched or costed: none beat this.

namespace {
constexpr int H = 512, W = 512, C = 3;
constexpr int HW = H * W;
constexpr int RMAX = 8;
constexpr int BX = 32, BY = 8;        // 256 threads
constexpr int V  = 4;                 // vertical outputs per thread (2 pairs)
constexpr int TW = BX;                // 32-wide output tile
constexpr int TH = BY * V;            // 32-tall output tile
constexpr int SW = TW + 2 * RMAX;     // 48
constexpr int SH = TH + 2 * RMAX;     // 48
constexpr int NTAP = 2 * RMAX + 1;    // 17
constexpr int NROW = V + 2 * RMAX;    // 20
constexpr float NEG_BIG = -1e30f;
constexpr float LOG2E = 1.4426950408889634f;
}

typedef unsigned long long u64;

__device__ __forceinline__ float ex2f(float x) {
    float y;
    asm("ex2.approx.ftz.f32 %0, %1;" : "=f"(y) : "f"(x));
    return y;
}
__device__ __forceinline__ u64 pack2(float lo, float hi) {
    u64 r;
    asm("mov.b64 %0, {%1, %2};" : "=l"(r) : "f"(lo), "f"(hi));
    return r;
}
__device__ __forceinline__ void unpack2(u64 v, float& lo, float& hi) {
    asm("mov.b64 {%0, %1}, %2;" : "=f"(lo), "=f"(hi) : "l"(v));
}
__device__ __forceinline__ u64 fma2(u64 a, u64 b, u64 c) {
    u64 d;
    asm("fma.rn.f32x2 %0, %1, %2, %3;" : "=l"(d) : "l"(a), "l"(b), "l"(c));
    return d;
}
__device__ __forceinline__ u64 add2(u64 a, u64 b) {
    u64 d;
    asm("add.rn.f32x2 %0, %1, %2;" : "=l"(d) : "l"(a), "l"(b));
    return d;
}

struct PairState {
    u64 ccx[2], ccy[2], ccz[2];   // packed A-scaled center rgb per pair
    u64 nx[2], ny[2], nz[2], dn[2];
};

// One halo row. dx^2 terms are compile-time FFMA immediates.
template<bool P01, bool P23>
__device__ __forceinline__ void process_row(const float4* __restrict__ row,
                                            float m /* -inv2s */,
                                            u64 rb0, u64 rb1, PairState& st)
{
    #pragma unroll
    for (int dx = 0; dx < NTAP; dx++) {
        float4 s = row[dx];
        const float d2 = (float)((dx - RMAX) * (dx - RMAX));
        float sw2 = fmaf(d2, m, s.w);          // FFMA-imm (rt=1)
        u64 sw22 = pack2(sw2, sw2);
        u64 sx2  = pack2(s.x, s.x);
        u64 sy2  = pack2(s.y, s.y);
        u64 sz2  = pack2(s.z, s.z);
        if (P01) {
            u64 arg = fma2(sz2, st.ccz[0],
                      fma2(sy2, st.ccy[0],
                      fma2(sx2, st.ccx[0], add2(sw22, rb0))));
            float a0, a1; unpack2(arg, a0, a1);
            u64 w2 = pack2(ex2f(a0), ex2f(a1));
            st.nx[0] = fma2(w2, sx2, st.nx[0]);
            st.ny[0] = fma2(w2, sy2, st.ny[0]);
            st.nz[0] = fma2(w2, sz2, st.nz[0]);
            st.dn[0] = add2(st.dn[0], w2);
        }
        if (P23) {
            u64 arg = fma2(sz2, st.ccz[1],
                      fma2(sy2, st.ccy[1],
                      fma2(sx2, st.ccx[1], add2(sw22, rb1))));
            float a0, a1; unpack2(arg, a0, a1);
            u64 w2 = pack2(ex2f(a0), ex2f(a1));
            st.nx[1] = fma2(w2, sx2, st.nx[1]);
            st.ny[1] = fma2(w2, sy2, st.ny[1]);
            st.nz[1] = fma2(w2, sz2, st.nz[1]);
            st.dn[1] = add2(st.dn[1], w2);
        }
    }
}

__global__ __launch_bounds__(256, 3)
void bilateral_kernel(const float* __restrict__ img,
                      const float* __restrict__ params,
                      float* __restrict__ out)
{
    __shared__ float4 tile[SH * SW];             // 36864 B
    __shared__ float  dym[NROW][V];              // thread-invariant row terms

    const int n   = blockIdx.z;
    const int tx  = threadIdx.x;
    const int ty  = threadIdx.y;
    const int tid = ty * BX + tx;

    const int x0 = blockIdx.x * TW - RMAX;
    const int y0 = blockIdx.y * TH - RMAX;

    const float* im = img + (size_t)n * C * HW;

    const int radius = ((((int)params[n * 3 + 0]) * 14 + 3) - 1) >> 1;
    const int r = radius < RMAX ? radius : RMAX;
    const float p1 = params[n * 3 + 1];
    const float p2 = params[n * 3 + 2];
    const float sc = fmaf(p1, 99.0f, 1.0f);
    const float ss = fmaf(p2, 99.0f, 1.0f);
    // 255^2 (reference pixel scaling) and log2(e) folded into constants.
    const float inv2c = 65025.0f * LOG2E / (2.0f * sc * sc);
    const float inv2s = LOG2E / (2.0f * ss * ss);
    const float m = -inv2s;
    const float A = 2.0f * inv2c;

    // Thread-invariant per-(row, v) spatial terms: dy^2*m, NEG_BIG if |dy|>8.
    if (tid < NROW * V) {
        int i = tid >> 2, v = tid & 3;
        int dy = i - RMAX - v;
        dym[i][v] = (dy >= -RMAX && dy <= RMAX)
                  ? ((float)(dy * dy)) * m : NEG_BIG;
    }

    // Halo load with edge clamp; .w = -inv2c * |rgb|^2.
    // Incremental (sy, sx) stepping: 256 = 5*48 + 16 (no div/mod per iter).
    {
        int sy = tid / SW, sx = tid - sy * SW;
        #pragma unroll
        for (int it = 0; it < (SH * SW + BX * BY - 1) / (BX * BY); it++) {
            int idx = sy * SW + sx;
            if (idx < SH * SW) {
                int gy = min(max(y0 + sy, 0), H - 1);
                int gx = min(max(x0 + sx, 0), W - 1);
                int b  = gy * W + gx;
                float a0 = im[b], a1 = im[b + HW], a2 = im[b + 2 * HW];
                float sq = fmaf(a2, a2, fmaf(a1, a1, a0 * a0));
                tile[idx] = make_float4(a0, a1, a2, -inv2c * sq);
            }
            sy += 5; sx += 16;
            if (sx >= SW) { sx -= SW; sy += 1; }
        }
    }
    __syncthreads();

    float* obase = out + (size_t)n * C * HW + blockIdx.x * TW + tx;
    const int oy0 = blockIdx.y * TH + ty * V;

    if (r == RMAX) {
        // ---------------- Hot path ----------------
        float4 cc[V];
        #pragma unroll
        for (int v = 0; v < V; v++)
            cc[v] = tile[(ty * V + v + RMAX) * SW + (tx + RMAX)];

        PairState st;
        #pragma unroll
        for (int p = 0; p < 2; p++) {
            st.ccx[p] = pack2(A * cc[2*p].x, A * cc[2*p+1].x);
            st.ccy[p] = pack2(A * cc[2*p].y, A * cc[2*p+1].y);
            st.ccz[p] = pack2(A * cc[2*p].z, A * cc[2*p+1].z);
            st.nx[p] = st.ny[p] = st.nz[p] = st.dn[p] = pack2(0.0f, 0.0f);
        }
        const u64 cw01 = pack2(cc[0].w, cc[1].w);
        const u64 cw23 = pack2(cc[2].w, cc[3].w);

        const float4* row = &tile[(ty * V) * SW + tx];

        // Head rows: only pair01 active (i = 0, 1).
        #pragma unroll
        for (int i = 0; i < 2; i++) {
            u64 rb0 = add2(cw01, *(const u64*)&dym[i][0]);
            process_row<true, false>(row, m, rb0, 0, st);
            row += SW;
        }
        // Mid rows: both pairs (i = 2..17).
        #pragma unroll 2
        for (int i = 2; i < 2 * RMAX + 2; i++) {
            u64 rb0 = add2(cw01, *(const u64*)&dym[i][0]);
            u64 rb1 = add2(cw23, *(const u64*)&dym[i][2]);
            process_row<true, true>(row, m, rb0, rb1, st);
            row += SW;
        }
        // Tail rows: only pair23 active (i = 18, 19).
        #pragma unroll
        for (int i = 2 * RMAX + 2; i < NROW; i++) {
            u64 rb1 = add2(cw23, *(const u64*)&dym[i][2]);
            process_row<false, true>(row, m, 0, rb1, st);
            row += SW;
        }

        #pragma unroll
        for (int p = 0; p < 2; p++) {
            float nxl, nxh, nyl, nyh, nzl, nzh, dl, dh;
            unpack2(st.nx[p], nxl, nxh);
            unpack2(st.ny[p], nyl, nyh);
            unpack2(st.nz[p], nzl, nzh);
            unpack2(st.dn[p], dl, dh);
            float il = __fdividef(1.0f, dl);
            float ih = __fdividef(1.0f, dh);
            float* o0 = obase + (oy0 + 2*p) * W;
            float* o1 = obase + (oy0 + 2*p + 1) * W;
            o0[0] = nxl * il;  o0[HW] = nyl * il;  o0[2*HW] = nzl * il;
            o1[0] = nxh * ih;  o1[HW] = nyh * ih;  o1[2*HW] = nzh * ih;
        }
    } else {
        // ---------------- Cold generic path (radius < 8) ----------------
        #pragma unroll 1
        for (int v = 0; v < V; v++) {
            const float4 c = tile[(ty * V + v + RMAX) * SW + (tx + RMAX)];
            float n0 = 0.0f, n1 = 0.0f, n2 = 0.0f, den = 0.0f;
            #pragma unroll 1
            for (int dy = -r; dy <= r; dy++) {
                const float4* grow = &tile[(ty * V + v + RMAX + dy) * SW + (tx + RMAX)];
                const float spy = (float)(dy * dy);
                #pragma unroll 1
                for (int dx = -r; dx <= r; dx++) {
                    float4 s = grow[dx];
                    float tt = fmaf(s.z, c.z, fmaf(s.y, c.y, s.x * c.x));
                    float sp2 = spy + (float)(dx * dx);
                    float arg = fmaf(tt, A, fmaf(sp2, m, s.w + c.w));
                    float w = ex2f(arg);
                    n0 = fmaf(w, s.x, n0);
                    n1 = fmaf(w, s.y, n1);
                    n2 = fmaf(w, s.z, n2);
                    den += w;
                }
            }
            float inv = __fdividef(1.0f, den);
            float* o = obase + (oy0 + v) * W;
            o[0] = n0 * inv;  o[HW] = n1 * inv;  o[2*HW] = n2 * inv;
        }
    }
}

extern "C" void kernel_launch(void* const* d_in, const int* in_sizes, int n_in,
                              void* d_out, int out_size) {
    const float* img    = (const float*)d_in[0];
    const float* params = (const float*)d_in[1];
    float*       outp   = (float*)d_out;
    const int N = in_sizes[1] / 3;   // 8 images
    dim3 block(BX, BY, 1);
    dim3 grid(W / TW, H / TH, N);
    bilateral_kernel<<<grid, block>>>(img, params, outp);
}

// round 16
// speedup vs baseline: 1.0237x; 1.0237x over previous
#include <cuda_runtime.h>

// OriginNoiseBilateral R16: 17x17 bilateral, 8x3x512x512 fp32 NCHW.
// The converged R14 optimum (V=4 as 2 packed f32x2 pairs, dym smem table,
// carry-stepped halo load, mid unroll x2) at finer CTA granularity:
// 128-thread blocks (BX=32, BY=4), 6 CTAs/SM -> same 24 warps/SM but twice
// as many independently-phased load/compute streams and half-size barrier
// groups. All per-tap math byte-identical to the verified optimum.

namespace {
constexpr int H = 512, W = 512, C = 3;
constexpr int HW = H * W;
constexpr int RMAX = 8;
constexpr int BX = 32, BY = 4;        // 128 threads
constexpr int NT = BX * BY;           // 128
constexpr int V  = 4;                 // vertical outputs per thread (2 pairs)
constexpr int TW = BX;                // 32-wide output tile
constexpr int TH = BY * V;            // 16-tall output tile
constexpr int SW = TW + 2 * RMAX;     // 48
constexpr int SH = TH + 2 * RMAX;     // 32
constexpr int NTAP = 2 * RMAX + 1;    // 17
constexpr int NROW = V + 2 * RMAX;    // 20
constexpr float NEG_BIG = -1e30f;
constexpr float LOG2E = 1.4426950408889634f;
}

typedef unsigned long long u64;

__device__ __forceinline__ float ex2f(float x) {
    float y;
    asm("ex2.approx.ftz.f32 %0, %1;" : "=f"(y) : "f"(x));
    return y;
}
__device__ __forceinline__ u64 pack2(float lo, float hi) {
    u64 r;
    asm("mov.b64 %0, {%1, %2};" : "=l"(r) : "f"(lo), "f"(hi));
    return r;
}
__device__ __forceinline__ void unpack2(u64 v, float& lo, float& hi) {
    asm("mov.b64 {%0, %1}, %2;" : "=f"(lo), "=f"(hi) : "l"(v));
}
__device__ __forceinline__ u64 fma2(u64 a, u64 b, u64 c) {
    u64 d;
    asm("fma.rn.f32x2 %0, %1, %2, %3;" : "=l"(d) : "l"(a), "l"(b), "l"(c));
    return d;
}
__device__ __forceinline__ u64 add2(u64 a, u64 b) {
    u64 d;
    asm("add.rn.f32x2 %0, %1, %2;" : "=l"(d) : "l"(a), "l"(b));
    return d;
}

struct PairState {
    u64 ccx[2], ccy[2], ccz[2];   // packed A-scaled center rgb per pair
    u64 nx[2], ny[2], nz[2], dn[2];
};

// One halo row. dx^2 terms are compile-time FFMA immediates.
template<bool P01, bool P23>
__device__ __forceinline__ void process_row(const float4* __restrict__ row,
                                            float m /* -inv2s */,
                                            u64 rb0, u64 rb1, PairState& st)
{
    #pragma unroll
    for (int dx = 0; dx < NTAP; dx++) {
        float4 s = row[dx];
        const float d2 = (float)((dx - RMAX) * (dx - RMAX));
        float sw2 = fmaf(d2, m, s.w);          // FFMA-imm (rt=1)
        u64 sw22 = pack2(sw2, sw2);
        u64 sx2  = pack2(s.x, s.x);
        u64 sy2  = pack2(s.y, s.y);
        u64 sz2  = pack2(s.z, s.z);
        if (P01) {
            u64 arg = fma2(sz2, st.ccz[0],
                      fma2(sy2, st.ccy[0],
                      fma2(sx2, st.ccx[0], add2(sw22, rb0))));
            float a0, a1; unpack2(arg, a0, a1);
            u64 w2 = pack2(ex2f(a0), ex2f(a1));
            st.nx[0] = fma2(w2, sx2, st.nx[0]);
            st.ny[0] = fma2(w2, sy2, st.ny[0]);
            st.nz[0] = fma2(w2, sz2, st.nz[0]);
            st.dn[0] = add2(st.dn[0], w2);
        }
        if (P23) {
            u64 arg = fma2(sz2, st.ccz[1],
                      fma2(sy2, st.ccy[1],
                      fma2(sx2, st.ccx[1], add2(sw22, rb1))));
            float a0, a1; unpack2(arg, a0, a1);
            u64 w2 = pack2(ex2f(a0), ex2f(a1));
            st.nx[1] = fma2(w2, sx2, st.nx[1]);
            st.ny[1] = fma2(w2, sy2, st.ny[1]);
            st.nz[1] = fma2(w2, sz2, st.nz[1]);
            st.dn[1] = add2(st.dn[1], w2);
        }
    }
}

__global__ __launch_bounds__(NT, 6)
void bilateral_kernel(const float* __restrict__ img,
                      const float* __restrict__ params,
                      float* __restrict__ out)
{
    __shared__ float4 tile[SH * SW];             // 32*48*16 = 24576 B
    __shared__ float  dym[NROW][V];              // thread-invariant row terms

    const int n   = blockIdx.z;
    const int tx  = threadIdx.x;
    const int ty  = threadIdx.y;
    const int tid = ty * BX + tx;

    const int x0 = blockIdx.x * TW - RMAX;
    const int y0 = blockIdx.y * TH - RMAX;

    const float* im = img + (size_t)n * C * HW;

    const int radius = ((((int)params[n * 3 + 0]) * 14 + 3) - 1) >> 1;
    const int r = radius < RMAX ? radius : RMAX;
    const float p1 = params[n * 3 + 1];
    const float p2 = params[n * 3 + 2];
    const float sc = fmaf(p1, 99.0f, 1.0f);
    const float ss = fmaf(p2, 99.0f, 1.0f);
    // 255^2 (reference pixel scaling) and log2(e) folded into constants.
    const float inv2c = 65025.0f * LOG2E / (2.0f * sc * sc);
    const float inv2s = LOG2E / (2.0f * ss * ss);
    const float m = -inv2s;
    const float A = 2.0f * inv2c;

    // Thread-invariant per-(row, v) spatial terms: dy^2*m, NEG_BIG if |dy|>8.
    if (tid < NROW * V) {
        int i = tid >> 2, v = tid & 3;
        int dy = i - RMAX - v;
        dym[i][v] = (dy >= -RMAX && dy <= RMAX)
                  ? ((float)(dy * dy)) * m : NEG_BIG;
    }

    // Halo load with edge clamp; .w = -inv2c * |rgb|^2.
    // Incremental (sy, sx) stepping: 128 = 2*48 + 32 (no div/mod per iter).
    {
        int sy = tid / SW, sx = tid - sy * SW;
        #pragma unroll
        for (int it = 0; it < (SH * SW) / NT; it++) {   // 1536/128 = 12 exact
            int idx = sy * SW + sx;
            int gy = min(max(y0 + sy, 0), H - 1);
            int gx = min(max(x0 + sx, 0), W - 1);
            int b  = gy * W + gx;
            float a0 = im[b], a1 = im[b + HW], a2 = im[b + 2 * HW];
            float sq = fmaf(a2, a2, fmaf(a1, a1, a0 * a0));
            tile[idx] = make_float4(a0, a1, a2, -inv2c * sq);
            sy += 2; sx += 32;
            if (sx >= SW) { sx -= SW; sy += 1; }
        }
    }
    __syncthreads();

    float* obase = out + (size_t)n * C * HW + blockIdx.x * TW + tx;
    const int oy0 = blockIdx.y * TH + ty * V;

    if (r == RMAX) {
        // ---------------- Hot path ----------------
        float4 cc[V];
        #pragma unroll
        for (int v = 0; v < V; v++)
            cc[v] = tile[(ty * V + v + RMAX) * SW + (tx + RMAX)];

        PairState st;
        #pragma unroll
        for (int p = 0; p < 2; p++) {
            st.ccx[p] = pack2(A * cc[2*p].x, A * cc[2*p+1].x);
            st.ccy[p] = pack2(A * cc[2*p].y, A * cc[2*p+1].y);
            st.ccz[p] = pack2(A * cc[2*p].z, A * cc[2*p+1].z);
            st.nx[p] = st.ny[p] = st.nz[p] = st.dn[p] = pack2(0.0f, 0.0f);
        }
        const u64 cw01 = pack2(cc[0].w, cc[1].w);
        const u64 cw23 = pack2(cc[2].w, cc[3].w);

        const float4* row = &tile[(ty * V) * SW + tx];

        // Head rows: only pair01 active (i = 0, 1).
        #pragma unroll
        for (int i = 0; i < 2; i++) {
            u64 rb0 = add2(cw01, *(const u64*)&dym[i][0]);
            process_row<true, false>(row, m, rb0, 0, st);
            row += SW;
        }
        // Mid rows: both pairs (i = 2..17).
        #pragma unroll 2
        for (int i = 2; i < 2 * RMAX + 2; i++) {
            u64 rb0 = add2(cw01, *(const u64*)&dym[i][0]);
            u64 rb1 = add2(cw23, *(const u64*)&dym[i][2]);
            process_row<true, true>(row, m, rb0, rb1, st);
            row += SW;
        }
        // Tail rows: only pair23 active (i = 18, 19).
        #pragma unroll
        for (int i = 2 * RMAX + 2; i < NROW; i++) {
            u64 rb1 = add2(cw23, *(const u64*)&dym[i][2]);
            process_row<false, true>(row, m, 0, rb1, st);
            row += SW;
        }

        #pragma unroll
        for (int p = 0; p < 2; p++) {
            float nxl, nxh, nyl, nyh, nzl, nzh, dl, dh;
            unpack2(st.nx[p], nxl, nxh);
            unpack2(st.ny[p], nyl, nyh);
            unpack2(st.nz[p], nzl, nzh);
            unpack2(st.dn[p], dl, dh);
            float il = __fdividef(1.0f, dl);
            float ih = __fdividef(1.0f, dh);
            float* o0 = obase + (oy0 + 2*p) * W;
            float* o1 = obase + (oy0 + 2*p + 1) * W;
            o0[0] = nxl * il;  o0[HW] = nyl * il;  o0[2*HW] = nzl * il;
            o1[0] = nxh * ih;  o1[HW] = nyh * ih;  o1[2*HW] = nzh * ih;
        }
    } else {
        // ---------------- Cold generic path (radius < 8) ----------------
        #pragma unroll 1
        for (int v = 0; v < V; v++) {
            const float4 c = tile[(ty * V + v + RMAX) * SW + (tx + RMAX)];
            float n0 = 0.0f, n1 = 0.0f, n2 = 0.0f, den = 0.0f;
            #pragma unroll 1
            for (int dy = -r; dy <= r; dy++) {
                const float4* grow = &tile[(ty * V + v + RMAX + dy) * SW + (tx + RMAX)];
                const float spy = (float)(dy * dy);
                #pragma unroll 1
                for (int dx = -r; dx <= r; dx++) {
                    float4 s = grow[dx];
                    float tt = fmaf(s.z, c.z, fmaf(s.y, c.y, s.x * c.x));
                    float sp2 = spy + (float)(dx * dx);
                    float arg = fmaf(tt, A, fmaf(sp2, m, s.w + c.w));
                    float w = ex2f(arg);
                    n0 = fmaf(w, s.x, n0);
                    n1 = fmaf(w, s.y, n1);
                    n2 = fmaf(w, s.z, n2);
                    den += w;
                }
            }
            float inv = __fdividef(1.0f, den);
            float* o = obase + (oy0 + v) * W;
            o[0] = n0 * inv;  o[HW] = n1 * inv;  o[2*HW] = n2 * inv;
        }
    }
}

extern "C" void kernel_launch(void* const* d_in, const int* in_sizes, int n_in,
                              void* d_out, int out_size) {
    const float* img    = (const float*)d_in[0];
    const float* params = (const float*)d_in[1];
    float*       outp   = (float*)d_out;
    const int N = in_sizes[1] / 3;   // 8 images
    dim3 block(BX, BY, 1);
    dim3 grid(W / TW, H / TH, N);
    bilateral_kernel<<<grid, block>>>(img, params, outp);
}